// round 14
// baseline (speedup 1.0000x reference)
#include <cuda_runtime.h>
#include <cstdint>

#define NB 4
#define NC 64
#define NH 256
#define NW 256
#define NPIX 65536
#define NWH 128
#define NPH 32768
#define NHEADS 4
#define ND 16
#define NC2 128
#define NC4 256

// ---- scratch (device globals: allocation-free rule) ----
static __device__ float g_q1[NB*NC*NPIX];
static __device__ float g_k1[NB*NC*NPIX];
static __device__ float g_v1[NB*NC*NPIX];
static __device__ float g_qs[NB*NC*NPH];
static __device__ float g_ks[NB*NC*NPH];
static __device__ float g_vs[NB*NC*NPH];
static __device__ float g_att[NB*NC*NPH];
static __device__ float g_m1v[NB*NC4*NPIX];
static __device__ float g_m2v[NB*NC4*NPIX];
static __device__ float g_kmax[NB*NC];
static __device__ float g_ksum[NB*NC];
static __device__ float g_ctx[NB*NHEADS*ND*ND];
static __device__ float g_rwt[NC*25*NC2];      // r_w -> [ci][tap][co]
static __device__ float g_m1wt[NC2*NC4];       // m1_w -> [ci][co]
static __device__ float g_m3wt[NC4*NC2];       // m3_w -> [ci][co]

__device__ __forceinline__ float gelu_f(float x){
    return 0.5f*x*(1.0f+erff(x*0.70710678118654752440f));
}
__device__ __forceinline__ uint32_t s2u(const void* p){
    uint32_t a;
    asm("{ .reg .u64 t; cvta.to.shared.u64 t, %1; cvt.u32.u64 %0, t; }" : "=r"(a) : "l"(p));
    return a;
}
__device__ __forceinline__ void cpa16(uint32_t dst, const void* src){
    asm volatile("cp.async.ca.shared.global [%0], [%1], 16;" :: "r"(dst), "l"(src));
}
#define CPA_COMMIT() asm volatile("cp.async.commit_group;")
#define CPA_WAIT1()  asm volatile("cp.async.wait_group 1;")
#define CPA_WAIT0()  asm volatile("cp.async.wait_group 0;")

// ---------------- K0: weight transposes + ctx zero ----------------
__global__ void k_prep(const float* __restrict__ rw, const float* __restrict__ m1w,
                       const float* __restrict__ m3w){
    int i = blockIdx.x*256 + threadIdx.x;
    if (i < 128*64*25){            // r_w [co][ci][tap] -> [ci][tap][co]
        int co = i/1600; int r = i - co*1600; int ci = r/25; int tap = r - ci*25;
        g_rwt[(ci*25+tap)*NC2 + co] = rw[i];
    }
    if (i < 256*128){
        int co = i>>7, ci = i&127;
        g_m1wt[ci*NC4 + co] = m1w[i];
    }
    if (i < 128*256){
        int co = i>>8, ci = i&255;
        g_m3wt[ci*NC2 + co] = m3w[i];
    }
    if (i < NB*NHEADS*ND*ND) g_ctx[i] = 0.f;
}

// ---------------- K1: fused q/k/v 1x1 convs ----------------
__global__ __launch_bounds__(256) void k_qkv1(
    const float* __restrict__ x1, const float* __restrict__ x2,
    const float* __restrict__ qw, const float* __restrict__ qb,
    const float* __restrict__ kw, const float* __restrict__ kb,
    const float* __restrict__ vw, const float* __restrict__ vb)
{
    __shared__ float4 Wsm[3072];
    int tid = threadIdx.x;
    for (int i = tid; i < 1024; i += 256){
        Wsm[i]       = ((const float4*)qw)[i];
        Wsm[1024+i]  = ((const float4*)kw)[i];
        Wsm[2048+i]  = ((const float4*)vw)[i];
    }
    __syncthreads();

    int pix = blockIdx.x*256 + tid;
    int b = pix >> 16; int ij = pix & 65535;
    int i_ = ij >> 8, j_ = ij & 255;
    int par = (i_ + j_) & 1;
    size_t base = (size_t)b*NC*NPIX + ij;

    float xr[64];
    const float* xin = x1 + base;
    #pragma unroll
    for (int c = 0; c < 64; c++) xr[c] = xin[(size_t)c*NPIX];

    const float4* wb4 = par ? (Wsm + 1024) : Wsm;
    float* dst = par ? g_k1 : g_q1;
    const float* bd = par ? kb : qb;

    #pragma unroll 4
    for (int co = 0; co < 64; co++){
        float acc = bd[co];
        #pragma unroll
        for (int c4 = 0; c4 < 16; c4++){
            float4 w = wb4[co*16 + c4];
            acc = fmaf(w.x, xr[4*c4+0], acc);
            acc = fmaf(w.y, xr[4*c4+1], acc);
            acc = fmaf(w.z, xr[4*c4+2], acc);
            acc = fmaf(w.w, xr[4*c4+3], acc);
        }
        dst[base + (size_t)co*NPIX] = acc;
    }

    const float* x2in = x2 + base;
    #pragma unroll
    for (int c = 0; c < 64; c++) xr[c] = x2in[(size_t)c*NPIX];
    #pragma unroll 4
    for (int co = 0; co < 64; co++){
        float acc = vb[co];
        #pragma unroll
        for (int c4 = 0; c4 < 16; c4++){
            float4 w = Wsm[2048 + co*16 + c4];
            acc = fmaf(w.x, xr[4*c4+0], acc);
            acc = fmaf(w.y, xr[4*c4+1], acc);
            acc = fmaf(w.z, xr[4*c4+2], acc);
            acc = fmaf(w.w, xr[4*c4+3], acc);
        }
        g_v1[base + (size_t)co*NPIX] = acc;
    }
}

// ---------------- K2: depthwise 3x3 at squeezed positions, 2 outputs/thread ----------------
__global__ __launch_bounds__(256) void k_dws(
    const float* __restrict__ q2w, const float* __restrict__ q2b,
    const float* __restrict__ k2w, const float* __restrict__ k2b,
    const float* __restrict__ v2w, const float* __restrict__ v2b,
    const float* __restrict__ qb1, const float* __restrict__ kb1)
{
    int z = blockIdx.y;
    const float* src; const float* w; const float* bias; float* dst; int asel;
    if (z == 0){ src=g_q1; w=q2w; bias=q2b; dst=g_qs; asel=0; }
    else if (z == 1){ src=g_k1; w=k2w; bias=k2b; dst=g_ks; asel=1; }
    else { src=g_v1; w=v2w; bias=v2b; dst=g_vs; asel=1; }

    int gid = blockIdx.x*256 + threadIdx.x;
    int jq = gid & 63; int i_ = (gid >> 6) & 255; int bc = gid >> 14;
    int c = bc & 63;
    int off = (i_ & 1) ^ asel;
    int j0 = 4*jq + off;
    float bval = (z==0) ? qb1[c] : (z==1 ? kb1[c] : 0.f);
    bool dense = (z==2);

    const float* s = src + (size_t)bc*NPIX;
    const float* wc = w + c*9;
    float* d2 = dst + (size_t)bc*NPH + i_*NWH + 2*jq;

    if (i_ > 0 && i_ < 255 && j0 >= 1 && j0 + 3 <= 255){
        float w00 = wc[0], w01 = wc[1], w02 = wc[2];
        float w10 = wc[3], w11 = wc[4], w12 = wc[5];
        float w20 = wc[6], w21 = wc[7], w22 = wc[8];
        const float* r0 = s + (i_-1)*NW + j0;
        const float* r1 = s + i_*NW + j0;
        const float* r2 = s + (i_+1)*NW + j0;
        float bb = bias[c];
        float a0, a1;
        if (dense){
            float t0m = r0[-1], t00 = r0[0], t01 = r0[1], t02 = r0[2], t03 = r0[3];
            float t1m = r1[-1], t10 = r1[0], t11 = r1[1], t12 = r1[2], t13 = r1[3];
            float t2m = r2[-1], t20 = r2[0], t21 = r2[1], t22 = r2[2], t23 = r2[3];
            a0 = bb;
            a0 = fmaf(w00, t0m, a0); a0 = fmaf(w01, t00, a0); a0 = fmaf(w02, t01, a0);
            a0 = fmaf(w10, t1m, a0); a0 = fmaf(w11, t10, a0); a0 = fmaf(w12, t11, a0);
            a0 = fmaf(w20, t2m, a0); a0 = fmaf(w21, t20, a0); a0 = fmaf(w22, t21, a0);
            a1 = bb;
            a1 = fmaf(w00, t01, a1); a1 = fmaf(w01, t02, a1); a1 = fmaf(w02, t03, a1);
            a1 = fmaf(w10, t11, a1); a1 = fmaf(w11, t12, a1); a1 = fmaf(w12, t13, a1);
            a1 = fmaf(w20, t21, a1); a1 = fmaf(w21, t22, a1); a1 = fmaf(w22, t23, a1);
        } else {
            float t0m = r0[-1], t01 = r0[1], t03 = r0[3];
            float t10 = r1[0],  t12 = r1[2];
            float t2m = r2[-1], t21 = r2[1], t23 = r2[3];
            float bterm = fmaf(w01 + w21 + w10 + w12, bval, bb);
            a0 = bterm;
            a0 = fmaf(w00, t0m, a0); a0 = fmaf(w02, t01, a0);
            a0 = fmaf(w11, t10, a0);
            a0 = fmaf(w20, t2m, a0); a0 = fmaf(w22, t21, a0);
            a1 = bterm;
            a1 = fmaf(w00, t01, a1); a1 = fmaf(w02, t03, a1);
            a1 = fmaf(w11, t12, a1);
            a1 = fmaf(w20, t21, a1); a1 = fmaf(w22, t23, a1);
        }
        d2[0] = a0; d2[1] = a1;
    } else {
        #pragma unroll
        for (int t = 0; t < 2; t++){
            int j_ = j0 + 2*t;
            float acc = bias[c];
            #pragma unroll
            for (int di = -1; di <= 1; di++)
                #pragma unroll
                for (int dj = -1; dj <= 1; dj++){
                    int ii = i_ + di, jj = j_ + dj;
                    if (ii >= 0 && ii < NH && jj >= 0 && jj < NW){
                        float ww = wc[(di+1)*3 + (dj+1)];
                        if (dense || (((di+dj)&1) == 0)) acc = fmaf(ww, s[ii*NW + jj], acc);
                        else                              acc = fmaf(ww, bval, acc);
                    }
                }
            d2[t] = acc;
        }
    }
}

// ---------------- K3: k softmax max only (sum deferred to ctx normalization) ----------------
__global__ __launch_bounds__(1024) void k_kstats(){
    int row = blockIdx.x;
    int tid = threadIdx.x;
    const float4* s4 = (const float4*)(g_ks + (size_t)row*NPH);
    __shared__ float red[32];

    float m = -1e30f;
    for (int i = tid; i < NPH/4; i += 1024){
        float4 v = s4[i];
        m = fmaxf(m, fmaxf(fmaxf(v.x, v.y), fmaxf(v.z, v.w)));
    }
    #pragma unroll
    for (int o = 16; o > 0; o >>= 1) m = fmaxf(m, __shfl_xor_sync(~0u, m, o));
    if ((tid & 31) == 0) red[tid >> 5] = m;
    __syncthreads();
    if (tid < 32){
        float t = red[tid];
        #pragma unroll
        for (int o = 16; o > 0; o >>= 1) t = fmaxf(t, __shfl_xor_sync(~0u, t, o));
        if (tid == 0) g_kmax[row] = t;
    }
}

// ---------------- K4: ctx_unnorm = exp(k-kmax) @ v^T; also accumulates ksum ----------------
__global__ __launch_bounds__(256) void k_ctx(){
    int bh = blockIdx.x;
    int split = blockIdx.y;
    int b = bh >> 2, hd = bh & 3;
    int crow = b*NC + hd*ND;
    int n0 = split * (NPH/16);

    __shared__ float ksm[16][65];
    __shared__ float vsm[16][65];
    __shared__ float kmx[16];
    __shared__ float srow[16][17];
    int tid = threadIdx.x;
    int d = tid & 15, e = tid >> 4;
    if (tid < 16) kmx[tid] = g_kmax[crow + tid];
    __syncthreads();

    float acc = 0.f;
    float psum = 0.f;                        // lane-partial of sum over n for row d (each e-slice covers distinct nn? no)
    for (int nb = 0; nb < NPH/16; nb += 64){
        __syncthreads();
        for (int idx = tid; idx < 1024; idx += 256){
            int dd = idx >> 6, nn = idx & 63;
            int n = n0 + nb + nn;
            ksm[dd][nn] = __expf(g_ks[(size_t)(crow+dd)*NPH + n] - kmx[dd]);
            vsm[dd][nn] = g_vs[(size_t)(crow+dd)*NPH + n];
        }
        __syncthreads();
        #pragma unroll
        for (int nn = 0; nn < 64; nn++)
            acc = fmaf(ksm[d][nn], vsm[e][nn], acc);
        // rows of ksm indexed by e cover all 16 d-rows once per thread-col; use e==0 threads? simpler: thread (d,e) sums ksm[d][nn] only for e==0
        if (e == 0){
            float s = 0.f;
            #pragma unroll
            for (int nn = 0; nn < 64; nn++) s += ksm[d][nn];
            psum += s;
        }
    }
    atomicAdd(&g_ctx[bh*256 + d*16 + e], acc);
    if (e == 0) atomicAdd(&g_ksum[crow + d], psum);
}

// ---------------- K5: q-softmax + att = (ctx/ksum)^T @ q ----------------
__global__ void k_att(){
    int bh = blockIdx.y; int b = bh >> 2, hd = bh & 3;
    int pos = blockIdx.x*256 + threadIdx.x;
    __shared__ float ctxs[256];
    int tid = threadIdx.x;
    {
        int d = tid >> 4;
        ctxs[tid] = g_ctx[bh*256 + tid] / g_ksum[(b*NC + hd*ND) + d];
    }
    __syncthreads();

    size_t base = ((size_t)(b*NC + hd*ND))*NPH + pos;
    float qv[16];
    float mx = -1e30f;
    #pragma unroll
    for (int d = 0; d < 16; d++){ qv[d] = g_qs[base + (size_t)d*NPH]; mx = fmaxf(mx, qv[d]); }
    float s = 0.f;
    #pragma unroll
    for (int d = 0; d < 16; d++){ qv[d] = __expf(qv[d] - mx); s += qv[d]; }
    float inv = 1.f / s;
    #pragma unroll
    for (int e = 0; e < 16; e++){
        float a = 0.f;
        #pragma unroll
        for (int d = 0; d < 16; d++) a = fmaf(ctxs[d*16 + e], qv[d], a);
        g_att[base + (size_t)e*NPH] = a * inv;
    }
}

// ---------------- K6: 5x5 conv (64 -> 128) on checkerboard-sparse att (R7 form) ----------------
__global__ __launch_bounds__(256) void k_conv5(const float* __restrict__ rb, float* __restrict__ out){
    __shared__ float attsm[1600];
    __shared__ float wsm[6400];
    int tid = threadIdx.x;
    int b = blockIdx.z >> 2, cog = blockIdx.z & 3;
    int i0 = blockIdx.y*16, j0 = blockIdx.x*16;

    int p = tid >> 7;
    int id = tid & 127; int ty = id >> 3; int txp = id & 7;
    int tx = 2*txp + ((ty + p) & 1);

    int tc[5];
    #pragma unroll
    for (int kj = 0; kj < 5; kj++) tc[kj] = ((tx + kj - 2) >> 1) + 1;

    float acc[32];
    #pragma unroll
    for (int c = 0; c < 32; c++) acc[c] = 0.f;

    for (int cc0 = 0; cc0 < 64; cc0 += 8){
        __syncthreads();
        for (int idx = tid; idx < 1600; idx += 256){
            int ci = idx/200; int r2 = idx - ci*200; int rr = r2/10; int cl = r2 - rr*10;
            int grow = i0 - 2 + rr; int gcol = (j0 >> 1) - 1 + cl;
            float v = 0.f;
            if (grow >= 0 && grow < NH && gcol >= 0 && gcol < NWH)
                v = g_att[((size_t)(b*NC + cc0 + ci)*NH + grow)*NWH + gcol];
            attsm[idx] = v;
        }
        for (int idx = tid; idx < 6400; idx += 256){
            int col = idx & 31; int t2 = idx >> 5;
            wsm[idx] = g_rwt[(size_t)(cc0*25 + t2)*NC2 + cog*32 + col];
        }
        __syncthreads();
        #pragma unroll 2
        for (int ci = 0; ci < 8; ci++){
            const float* A = attsm + ci*200 + ty*10;
            const float4* Wf = (const float4*)(wsm + ci*800);
            if (p == 0){
                static const int KI[13] = {0,0,0,1,1,2,2,2,3,3,4,4,4};
                static const int KJ[13] = {0,2,4,1,3,0,2,4,1,3,0,2,4};
                #pragma unroll
                for (int t = 0; t < 13; t++){
                    float a = A[KI[t]*10 + tc[KJ[t]]];
                    const float4* wp = Wf + (KI[t]*5 + KJ[t])*8;
                    #pragma unroll
                    for (int c4 = 0; c4 < 8; c4++){
                        float4 w = wp[c4];
                        acc[4*c4+0] = fmaf(a, w.x, acc[4*c4+0]);
                        acc[4*c4+1] = fmaf(a, w.y, acc[4*c4+1]);
                        acc[4*c4+2] = fmaf(a, w.z, acc[4*c4+2]);
                        acc[4*c4+3] = fmaf(a, w.w, acc[4*c4+3]);
                    }
                }
            } else {
                static const int KI2[12] = {0,0,1,1,1,2,2,3,3,3,4,4};
                static const int KJ2[12] = {1,3,0,2,4,1,3,0,2,4,1,3};
                #pragma unroll
                for (int t = 0; t < 12; t++){
                    float a = A[KI2[t]*10 + tc[KJ2[t]]];
                    const float4* wp = Wf + (KI2[t]*5 + KJ2[t])*8;
                    #pragma unroll
                    for (int c4 = 0; c4 < 8; c4++){
                        float4 w = wp[c4];
                        acc[4*c4+0] = fmaf(a, w.x, acc[4*c4+0]);
                        acc[4*c4+1] = fmaf(a, w.y, acc[4*c4+1]);
                        acc[4*c4+2] = fmaf(a, w.z, acc[4*c4+2]);
                        acc[4*c4+3] = fmaf(a, w.w, acc[4*c4+3]);
                    }
                }
            }
        }
    }
    int i_ = i0 + ty, j_ = j0 + tx;
    size_t ob = ((size_t)(b*NC2 + cog*32)*NH + i_)*NW + j_;
    #pragma unroll
    for (int c = 0; c < 32; c++)
        out[ob + (size_t)c*NPIX] = acc[c] + rb[cog*32 + c];
}

// ---------------- K7: m1 = gelu(1x1 128->256), cp.async double-buffered ----------------
__global__ __launch_bounds__(256) void k_gemm_m1(const float* __restrict__ X, const float* __restrict__ bias){
    __shared__ float Xs[2][16][132];
    __shared__ float Ws[2][16][132];
    int tid = threadIdx.x; int tx = tid & 15, ty = tid >> 4;
    int cot = blockIdx.x;
    int px0 = blockIdx.y*128;
    int b = blockIdx.z;
    float acc[8][8];
    #pragma unroll
    for (int i = 0; i < 8; i++)
        #pragma unroll
        for (int j = 0; j < 8; j++) acc[i][j] = 0.f;

    const float* Xg = X + (size_t)b*NC2*NPIX + px0;
    int f0 = tid, f1 = tid + 256;
    int k_0 = f0 >> 5, c_0 = (f0 & 31)*4;
    int k_1 = f1 >> 5, c_1 = (f1 & 31)*4;

    cpa16(s2u(&Xs[0][k_0][c_0]), Xg + (size_t)k_0*NPIX + c_0);
    cpa16(s2u(&Xs[0][k_1][c_1]), Xg + (size_t)k_1*NPIX + c_1);
    cpa16(s2u(&Ws[0][k_0][c_0]), &g_m1wt[(size_t)k_0*NC4 + cot*128 + c_0]);
    cpa16(s2u(&Ws[0][k_1][c_1]), &g_m1wt[(size_t)k_1*NC4 + cot*128 + c_1]);
    CPA_COMMIT();

    for (int s = 0; s < 8; s++){
        int buf = s & 1;
        if (s < 7){
            int nb = buf ^ 1, k0 = (s+1)*16;
            cpa16(s2u(&Xs[nb][k_0][c_0]), Xg + (size_t)(k0+k_0)*NPIX + c_0);
            cpa16(s2u(&Xs[nb][k_1][c_1]), Xg + (size_t)(k0+k_1)*NPIX + c_1);
            cpa16(s2u(&Ws[nb][k_0][c_0]), &g_m1wt[(size_t)(k0+k_0)*NC4 + cot*128 + c_0]);
            cpa16(s2u(&Ws[nb][k_1][c_1]), &g_m1wt[(size_t)(k0+k_1)*NC4 + cot*128 + c_1]);
            CPA_COMMIT();
            CPA_WAIT1();
        } else {
            CPA_WAIT0();
        }
        __syncthreads();
        #pragma unroll
        for (int k = 0; k < 16; k++){
            float4 x0 = *(const float4*)&Xs[buf][k][tx*8];
            float4 x1 = *(const float4*)&Xs[buf][k][tx*8+4];
            float4 w0 = *(const float4*)&Ws[buf][k][ty*8];
            float4 w1 = *(const float4*)&Ws[buf][k][ty*8+4];
            float xv[8] = {x0.x,x0.y,x0.z,x0.w,x1.x,x1.y,x1.z,x1.w};
            float wv[8] = {w0.x,w0.y,w0.z,w0.w,w1.x,w1.y,w1.z,w1.w};
            #pragma unroll
            for (int i = 0; i < 8; i++)
                #pragma unroll
                for (int j = 0; j < 8; j++)
                    acc[i][j] = fmaf(wv[i], xv[j], acc[i][j]);
        }
        __syncthreads();
    }
    #pragma unroll
    for (int i = 0; i < 8; i++){
        int co = cot*128 + ty*8 + i;
        float bb = bias[co];
        float* dst = &g_m1v[((size_t)(b*NC4 + co))*NPIX + px0 + tx*8];
        float4 o0, o1;
        o0.x = gelu_f(acc[i][0]+bb); o0.y = gelu_f(acc[i][1]+bb);
        o0.z = gelu_f(acc[i][2]+bb); o0.w = gelu_f(acc[i][3]+bb);
        o1.x = gelu_f(acc[i][4]+bb); o1.y = gelu_f(acc[i][5]+bb);
        o1.z = gelu_f(acc[i][6]+bb); o1.w = gelu_f(acc[i][7]+bb);
        *(float4*)dst = o0;
        *(float4*)(dst+4) = o1;
    }
}

// ---------------- K8: m2 = gelu(depthwise 3x3 on 256 ch), 4 px/thread float4 ----------------
__global__ __launch_bounds__(256) void k_m2dw(const float* __restrict__ w, const float* __restrict__ bias){
    int gid = blockIdx.x*256 + threadIdx.x;
    int jq = gid & 63; int i_ = (gid >> 6) & 255; int bc = gid >> 14; int c = bc & 255;
    int j4 = jq*4;
    const float* s = g_m1v + (size_t)bc*NPIX;
    float* dsto = g_m2v + (size_t)bc*NPIX + i_*NW + j4;
    const float* wc = w + c*9;
    float bb = bias[c];

    if (i_ > 0 && i_ < 255 && j4 >= 4 && j4 <= 248){
        float a0 = bb, a1 = bb, a2 = bb, a3 = bb;
        #pragma unroll
        for (int r = 0; r < 3; r++){
            const float* row = s + (i_ - 1 + r)*NW + j4;
            float4 m = *(const float4*)row;
            float l = row[-1], h = row[4];
            float w0 = wc[r*3], w1 = wc[r*3+1], w2 = wc[r*3+2];
            a0 = fmaf(w0, l,   a0); a0 = fmaf(w1, m.x, a0); a0 = fmaf(w2, m.y, a0);
            a1 = fmaf(w0, m.x, a1); a1 = fmaf(w1, m.y, a1); a1 = fmaf(w2, m.z, a1);
            a2 = fmaf(w0, m.y, a2); a2 = fmaf(w1, m.z, a2); a2 = fmaf(w2, m.w, a2);
            a3 = fmaf(w0, m.z, a3); a3 = fmaf(w1, m.w, a3); a3 = fmaf(w2, h,   a3);
        }
        float4 o;
        o.x = gelu_f(a0); o.y = gelu_f(a1); o.z = gelu_f(a2); o.w = gelu_f(a3);
        *(float4*)dsto = o;
    } else {
        #pragma unroll
        for (int t = 0; t < 4; t++){
            int j_ = j4 + t;
            float acc = bb;
            #pragma unroll
            for (int di = -1; di <= 1; di++)
                #pragma unroll
                for (int dj = -1; dj <= 1; dj++){
                    int ii = i_ + di, jj = j_ + dj;
                    if (ii >= 0 && ii < NH && jj >= 0 && jj < NW)
                        acc = fmaf(wc[(di+1)*3 + (dj+1)], s[ii*NW + jj], acc);
                }
            dsto[t] = gelu_f(acc);
        }
    }
}

// ---------------- K9: out += bias + 1x1 256->128, cp.async double-buffered ----------------
__global__ __launch_bounds__(256) void k_gemm_m3(const float* __restrict__ bias, float* __restrict__ out){
    __shared__ float Xs[2][16][132];
    __shared__ float Ws[2][16][132];
    int tid = threadIdx.x; int tx = tid & 15, ty = tid >> 4;
    int px0 = blockIdx.y*128;
    int b = blockIdx.z;
    float acc[8][8];
    #pragma unroll
    for (int i = 0; i < 8; i++)
        #pragma unroll
        for (int j = 0; j < 8; j++) acc[i][j] = 0.f;

    const float* Xg = g_m2v + (size_t)b*NC4*NPIX + px0;
    int f0 = tid, f1 = tid + 256;
    int k_0 = f0 >> 5, c_0 = (f0 & 31)*4;
    int k_1 = f1 >> 5, c_1 = (f1 & 31)*4;

    cpa16(s2u(&Xs[0][k_0][c_0]), Xg + (size_t)k_0*NPIX + c_0);
    cpa16(s2u(&Xs[0][k_1][c_1]), Xg + (size_t)k_1*NPIX + c_1);
    cpa16(s2u(&Ws[0][k_0][c_0]), &g_m3wt[(size_t)k_0*NC2 + c_0]);
    cpa16(s2u(&Ws[0][k_1][c_1]), &g_m3wt[(size_t)k_1*NC2 + c_1]);
    CPA_COMMIT();

    for (int s = 0; s < 16; s++){
        int buf = s & 1;
        if (s < 15){
            int nb = buf ^ 1, k0 = (s+1)*16;
            cpa16(s2u(&Xs[nb][k_0][c_0]), Xg + (size_t)(k0+k_0)*NPIX + c_0);
            cpa16(s2u(&Xs[nb][k_1][c_1]), Xg + (size_t)(k0+k_1)*NPIX + c_1);
            cpa16(s2u(&Ws[nb][k_0][c_0]), &g_m3wt[(size_t)(k0+k_0)*NC2 + c_0]);
            cpa16(s2u(&Ws[nb][k_1][c_1]), &g_m3wt[(size_t)(k0+k_1)*NC2 + c_1]);
            CPA_COMMIT();
            CPA_WAIT1();
        } else {
            CPA_WAIT0();
        }
        __syncthreads();
        #pragma unroll
        for (int k = 0; k < 16; k++){
            float4 x0 = *(const float4*)&Xs[buf][k][tx*8];
            float4 x1 = *(const float4*)&Xs[buf][k][tx*8+4];
            float4 w0 = *(const float4*)&Ws[buf][k][ty*8];
            float4 w1 = *(const float4*)&Ws[buf][k][ty*8+4];
            float xv[8] = {x0.x,x0.y,x0.z,x0.w,x1.x,x1.y,x1.z,x1.w};
            float wv[8] = {w0.x,w0.y,w0.z,w0.w,w1.x,w1.y,w1.z,w1.w};
            #pragma unroll
            for (int i = 0; i < 8; i++)
                #pragma unroll
                for (int j = 0; j < 8; j++)
                    acc[i][j] = fmaf(wv[i], xv[j], acc[i][j]);
        }
        __syncthreads();
    }
    #pragma unroll
    for (int i = 0; i < 8; i++){
        int co = ty*8 + i;
        float bb = bias[co];
        float* dst = &out[((size_t)(b*NC2 + co))*NPIX + px0 + tx*8];
        float4 r0 = *(const float4*)dst;
        float4 r1 = *(const float4*)(dst+4);
        float4 o0, o1;
        o0.x = acc[i][0]+bb+r0.x; o0.y = acc[i][1]+bb+r0.y;
        o0.z = acc[i][2]+bb+r0.z; o0.w = acc[i][3]+bb+r0.w;
        o1.x = acc[i][4]+bb+r1.x; o1.y = acc[i][5]+bb+r1.y;
        o1.z = acc[i][6]+bb+r1.z; o1.w = acc[i][7]+bb+r1.w;
        *(float4*)dst = o0;
        *(float4*)(dst+4) = o1;
    }
}

// zero ksum before ctx accumulation
__global__ void k_zsum(){
    int i = blockIdx.x*256 + threadIdx.x;
    if (i < NB*NC) g_ksum[i] = 0.f;
}

extern "C" void kernel_launch(void* const* d_in, const int* in_sizes, int n_in,
                              void* d_out, int out_size){
    const float* x1  = (const float*)d_in[0];
    const float* x2  = (const float*)d_in[1];
    const float* q1w = (const float*)d_in[2];  const float* q1b = (const float*)d_in[3];
    const float* q2w = (const float*)d_in[4];  const float* q2b = (const float*)d_in[5];
    const float* k1w = (const float*)d_in[6];  const float* k1b = (const float*)d_in[7];
    const float* k2w = (const float*)d_in[8];  const float* k2b = (const float*)d_in[9];
    const float* v1w = (const float*)d_in[10]; const float* v1b = (const float*)d_in[11];
    const float* v2w = (const float*)d_in[12]; const float* v2b = (const float*)d_in[13];
    const float* rw  = (const float*)d_in[14]; const float* rb  = (const float*)d_in[15];
    const float* m1w = (const float*)d_in[16]; const float* m1b = (const float*)d_in[17];
    const float* m2w = (const float*)d_in[18]; const float* m2b = (const float*)d_in[19];
    const float* m3w = (const float*)d_in[20]; const float* m3b = (const float*)d_in[21];
    float* out = (float*)d_out;

    k_prep<<<800, 256>>>(rw, m1w, m3w);
    k_zsum<<<1, 256>>>();
    k_qkv1<<<1024, 256>>>(x1, x2, q1w, q1b, k1w, k1b, v1w, v1b);
    k_dws<<<dim3(16384, 3), 256>>>(q2w, q2b, k2w, k2b, v2w, v2b, q1b, k1b);
    k_kstats<<<256, 1024>>>();
    k_ctx<<<dim3(16, 16), 256>>>();
    k_att<<<dim3(128, 16), 256>>>();
    k_conv5<<<dim3(16, 16, 16), 256>>>(rb, out);
    k_gemm_m1<<<dim3(2, 512, 4), 256>>>(out, m1b);
    k_m2dw<<<65536, 256>>>(m2w, m2b);
    k_gemm_m3<<<dim3(1, 512, 4), 256>>>(m3b, out);
}

// round 16
// speedup vs baseline: 1.6041x; 1.6041x over previous
#include <cuda_runtime.h>
#include <cstdint>

#define NB 4
#define NC 64
#define NH 256
#define NW 256
#define NPIX 65536
#define NWH 128
#define NPH 32768
#define NHEADS 4
#define ND 16
#define NC2 128
#define NC4 256

// ---- scratch (device globals: allocation-free rule) ----
static __device__ float g_q1[NB*NC*NPIX];
static __device__ float g_k1[NB*NC*NPIX];
static __device__ float g_v1[NB*NC*NPIX];
static __device__ float g_qs[NB*NC*NPH];
static __device__ float g_ks[NB*NC*NPH];
static __device__ float g_vs[NB*NC*NPH];
static __device__ float g_att[NB*NC*NPH];
static __device__ float g_m1v[NB*NC4*NPIX];
static __device__ float g_m2v[NB*NC4*NPIX];
static __device__ float g_kmax[NB*NC];
static __device__ float g_ksum[NB*NC];
static __device__ float g_ctx[NB*NHEADS*ND*ND];
static __device__ float g_rwt[NC*25*NC2];      // r_w -> [ci][tap][co]
static __device__ float g_m1wt[NC2*NC4];       // m1_w -> [ci][co]
static __device__ float g_m3wt[NC4*NC2];       // m3_w -> [ci][co]

__device__ __forceinline__ float gelu_f(float x){
    return 0.5f*x*(1.0f+erff(x*0.70710678118654752440f));
}
__device__ __forceinline__ uint32_t s2u(const void* p){
    uint32_t a;
    asm("{ .reg .u64 t; cvta.to.shared.u64 t, %1; cvt.u32.u64 %0, t; }" : "=r"(a) : "l"(p));
    return a;
}
__device__ __forceinline__ void cpa16(uint32_t dst, const void* src){
    asm volatile("cp.async.ca.shared.global [%0], [%1], 16;" :: "r"(dst), "l"(src));
}
#define CPA_COMMIT() asm volatile("cp.async.commit_group;")
#define CPA_WAIT1()  asm volatile("cp.async.wait_group 1;")
#define CPA_WAIT0()  asm volatile("cp.async.wait_group 0;")

// ---------------- K0: weight transposes + ctx zero ----------------
__global__ void k_prep(const float* __restrict__ rw, const float* __restrict__ m1w,
                       const float* __restrict__ m3w){
    int i = blockIdx.x*256 + threadIdx.x;
    if (i < 128*64*25){            // r_w [co][ci][tap] -> [ci][tap][co]
        int co = i/1600; int r = i - co*1600; int ci = r/25; int tap = r - ci*25;
        g_rwt[(ci*25+tap)*NC2 + co] = rw[i];
    }
    if (i < 256*128){
        int co = i>>7, ci = i&127;
        g_m1wt[ci*NC4 + co] = m1w[i];
    }
    if (i < 128*256){
        int co = i>>8, ci = i&255;
        g_m3wt[ci*NC2 + co] = m3w[i];
    }
    if (i < NB*NHEADS*ND*ND) g_ctx[i] = 0.f;
}

// ---------------- K1: fused q/k/v 1x1 convs ----------------
__global__ __launch_bounds__(256) void k_qkv1(
    const float* __restrict__ x1, const float* __restrict__ x2,
    const float* __restrict__ qw, const float* __restrict__ qb,
    const float* __restrict__ kw, const float* __restrict__ kb,
    const float* __restrict__ vw, const float* __restrict__ vb)
{
    __shared__ float4 Wsm[3072];
    int tid = threadIdx.x;
    for (int i = tid; i < 1024; i += 256){
        Wsm[i]       = ((const float4*)qw)[i];
        Wsm[1024+i]  = ((const float4*)kw)[i];
        Wsm[2048+i]  = ((const float4*)vw)[i];
    }
    __syncthreads();

    int pix = blockIdx.x*256 + tid;
    int b = pix >> 16; int ij = pix & 65535;
    int i_ = ij >> 8, j_ = ij & 255;
    int par = (i_ + j_) & 1;
    size_t base = (size_t)b*NC*NPIX + ij;

    float xr[64];
    const float* xin = x1 + base;
    #pragma unroll
    for (int c = 0; c < 64; c++) xr[c] = xin[(size_t)c*NPIX];

    const float4* wb4 = par ? (Wsm + 1024) : Wsm;
    float* dst = par ? g_k1 : g_q1;
    const float* bd = par ? kb : qb;

    #pragma unroll 4
    for (int co = 0; co < 64; co++){
        float acc = bd[co];
        #pragma unroll
        for (int c4 = 0; c4 < 16; c4++){
            float4 w = wb4[co*16 + c4];
            acc = fmaf(w.x, xr[4*c4+0], acc);
            acc = fmaf(w.y, xr[4*c4+1], acc);
            acc = fmaf(w.z, xr[4*c4+2], acc);
            acc = fmaf(w.w, xr[4*c4+3], acc);
        }
        dst[base + (size_t)co*NPIX] = acc;
    }

    const float* x2in = x2 + base;
    #pragma unroll
    for (int c = 0; c < 64; c++) xr[c] = x2in[(size_t)c*NPIX];
    #pragma unroll 4
    for (int co = 0; co < 64; co++){
        float acc = vb[co];
        #pragma unroll
        for (int c4 = 0; c4 < 16; c4++){
            float4 w = Wsm[2048 + co*16 + c4];
            acc = fmaf(w.x, xr[4*c4+0], acc);
            acc = fmaf(w.y, xr[4*c4+1], acc);
            acc = fmaf(w.z, xr[4*c4+2], acc);
            acc = fmaf(w.w, xr[4*c4+3], acc);
        }
        g_v1[base + (size_t)co*NPIX] = acc;
    }
}

// ---------------- K2: depthwise 3x3 at squeezed positions, 2 outputs/thread ----------------
__global__ __launch_bounds__(256) void k_dws(
    const float* __restrict__ q2w, const float* __restrict__ q2b,
    const float* __restrict__ k2w, const float* __restrict__ k2b,
    const float* __restrict__ v2w, const float* __restrict__ v2b,
    const float* __restrict__ qb1, const float* __restrict__ kb1)
{
    int z = blockIdx.y;
    const float* src; const float* w; const float* bias; float* dst; int asel;
    if (z == 0){ src=g_q1; w=q2w; bias=q2b; dst=g_qs; asel=0; }
    else if (z == 1){ src=g_k1; w=k2w; bias=k2b; dst=g_ks; asel=1; }
    else { src=g_v1; w=v2w; bias=v2b; dst=g_vs; asel=1; }

    int gid = blockIdx.x*256 + threadIdx.x;
    int jq = gid & 63; int i_ = (gid >> 6) & 255; int bc = gid >> 14;
    int c = bc & 63;
    int off = (i_ & 1) ^ asel;
    int j0 = 4*jq + off;
    float bval = (z==0) ? qb1[c] : (z==1 ? kb1[c] : 0.f);
    bool dense = (z==2);

    const float* s = src + (size_t)bc*NPIX;
    const float* wc = w + c*9;
    float* d2 = dst + (size_t)bc*NPH + i_*NWH + 2*jq;

    if (i_ > 0 && i_ < 255 && j0 >= 1 && j0 + 3 <= 255){
        float w00 = wc[0], w01 = wc[1], w02 = wc[2];
        float w10 = wc[3], w11 = wc[4], w12 = wc[5];
        float w20 = wc[6], w21 = wc[7], w22 = wc[8];
        const float* r0 = s + (i_-1)*NW + j0;
        const float* r1 = s + i_*NW + j0;
        const float* r2 = s + (i_+1)*NW + j0;
        float bb = bias[c];
        float a0, a1;
        if (dense){
            float t0m = r0[-1], t00 = r0[0], t01 = r0[1], t02 = r0[2], t03 = r0[3];
            float t1m = r1[-1], t10 = r1[0], t11 = r1[1], t12 = r1[2], t13 = r1[3];
            float t2m = r2[-1], t20 = r2[0], t21 = r2[1], t22 = r2[2], t23 = r2[3];
            a0 = bb;
            a0 = fmaf(w00, t0m, a0); a0 = fmaf(w01, t00, a0); a0 = fmaf(w02, t01, a0);
            a0 = fmaf(w10, t1m, a0); a0 = fmaf(w11, t10, a0); a0 = fmaf(w12, t11, a0);
            a0 = fmaf(w20, t2m, a0); a0 = fmaf(w21, t20, a0); a0 = fmaf(w22, t21, a0);
            a1 = bb;
            a1 = fmaf(w00, t01, a1); a1 = fmaf(w01, t02, a1); a1 = fmaf(w02, t03, a1);
            a1 = fmaf(w10, t11, a1); a1 = fmaf(w11, t12, a1); a1 = fmaf(w12, t13, a1);
            a1 = fmaf(w20, t21, a1); a1 = fmaf(w21, t22, a1); a1 = fmaf(w22, t23, a1);
        } else {
            float t0m = r0[-1], t01 = r0[1], t03 = r0[3];
            float t10 = r1[0],  t12 = r1[2];
            float t2m = r2[-1], t21 = r2[1], t23 = r2[3];
            float bterm = fmaf(w01 + w21 + w10 + w12, bval, bb);
            a0 = bterm;
            a0 = fmaf(w00, t0m, a0); a0 = fmaf(w02, t01, a0);
            a0 = fmaf(w11, t10, a0);
            a0 = fmaf(w20, t2m, a0); a0 = fmaf(w22, t21, a0);
            a1 = bterm;
            a1 = fmaf(w00, t01, a1); a1 = fmaf(w02, t03, a1);
            a1 = fmaf(w11, t12, a1);
            a1 = fmaf(w20, t21, a1); a1 = fmaf(w22, t23, a1);
        }
        d2[0] = a0; d2[1] = a1;
    } else {
        #pragma unroll
        for (int t = 0; t < 2; t++){
            int j_ = j0 + 2*t;
            float acc = bias[c];
            #pragma unroll
            for (int di = -1; di <= 1; di++)
                #pragma unroll
                for (int dj = -1; dj <= 1; dj++){
                    int ii = i_ + di, jj = j_ + dj;
                    if (ii >= 0 && ii < NH && jj >= 0 && jj < NW){
                        float ww = wc[(di+1)*3 + (dj+1)];
                        if (dense || (((di+dj)&1) == 0)) acc = fmaf(ww, s[ii*NW + jj], acc);
                        else                              acc = fmaf(ww, bval, acc);
                    }
                }
            d2[t] = acc;
        }
    }
}

// ---------------- K3: k softmax stats ----------------
__global__ __launch_bounds__(1024) void k_kstats(){
    int row = blockIdx.x;
    int tid = threadIdx.x;
    const float4* s4 = (const float4*)(g_ks + (size_t)row*NPH);
    __shared__ float red[32];

    float m = -1e30f;
    for (int i = tid; i < NPH/4; i += 1024){
        float4 v = s4[i];
        m = fmaxf(m, fmaxf(fmaxf(v.x, v.y), fmaxf(v.z, v.w)));
    }
    #pragma unroll
    for (int o = 16; o > 0; o >>= 1) m = fmaxf(m, __shfl_xor_sync(~0u, m, o));
    if ((tid & 31) == 0) red[tid >> 5] = m;
    __syncthreads();
    if (tid < 32){
        float t = red[tid];
        #pragma unroll
        for (int o = 16; o > 0; o >>= 1) t = fmaxf(t, __shfl_xor_sync(~0u, t, o));
        if (tid == 0) red[0] = t;
    }
    __syncthreads();
    m = red[0];
    __syncthreads();

    float sum = 0.f;
    for (int i = tid; i < NPH/4; i += 1024){
        float4 v = s4[i];
        sum += __expf(v.x - m) + __expf(v.y - m) + __expf(v.z - m) + __expf(v.w - m);
    }
    #pragma unroll
    for (int o = 16; o > 0; o >>= 1) sum += __shfl_xor_sync(~0u, sum, o);
    if ((tid & 31) == 0) red[tid >> 5] = sum;
    __syncthreads();
    if (tid < 32){
        float t = red[tid];
        #pragma unroll
        for (int o = 16; o > 0; o >>= 1) t += __shfl_xor_sync(~0u, t, o);
        if (tid == 0){ g_kmax[row] = m; g_ksum[row] = t; }
    }
}

// ---------------- K4: ctx = softmax(k) @ v^T ----------------
__global__ __launch_bounds__(256) void k_ctx(){
    int bh = blockIdx.x;
    int split = blockIdx.y;
    int b = bh >> 2, hd = bh & 3;
    int crow = b*NC + hd*ND;
    int n0 = split * (NPH/16);

    __shared__ float ksm[16][65];
    __shared__ float vsm[16][65];
    __shared__ float kmx[16], kin[16];
    int tid = threadIdx.x;
    int d = tid & 15, e = tid >> 4;
    if (tid < 16){ kmx[tid] = g_kmax[crow + tid]; kin[tid] = 1.f / g_ksum[crow + tid]; }
    __syncthreads();

    float acc = 0.f;
    for (int nb = 0; nb < NPH/16; nb += 64){
        __syncthreads();
        for (int idx = tid; idx < 1024; idx += 256){
            int dd = idx >> 6, nn = idx & 63;
            int n = n0 + nb + nn;
            ksm[dd][nn] = __expf(g_ks[(size_t)(crow+dd)*NPH + n] - kmx[dd]) * kin[dd];
            vsm[dd][nn] = g_vs[(size_t)(crow+dd)*NPH + n];
        }
        __syncthreads();
        #pragma unroll
        for (int nn = 0; nn < 64; nn++)
            acc = fmaf(ksm[d][nn], vsm[e][nn], acc);
    }
    atomicAdd(&g_ctx[bh*256 + d*16 + e], acc);
}

// ---------------- K5: q-softmax + att = ctx^T @ q ----------------
__global__ void k_att(){
    int bh = blockIdx.y; int b = bh >> 2, hd = bh & 3;
    int pos = blockIdx.x*256 + threadIdx.x;
    __shared__ float ctxs[256];
    ctxs[threadIdx.x] = g_ctx[bh*256 + threadIdx.x];
    __syncthreads();

    size_t base = ((size_t)(b*NC + hd*ND))*NPH + pos;
    float qv[16];
    float mx = -1e30f;
    #pragma unroll
    for (int d = 0; d < 16; d++){ qv[d] = g_qs[base + (size_t)d*NPH]; mx = fmaxf(mx, qv[d]); }
    float s = 0.f;
    #pragma unroll
    for (int d = 0; d < 16; d++){ qv[d] = __expf(qv[d] - mx); s += qv[d]; }
    float inv = 1.f / s;
    #pragma unroll
    for (int e = 0; e < 16; e++){
        float a = 0.f;
        #pragma unroll
        for (int d = 0; d < 16; d++) a = fmaf(ctxs[d*16 + e], qv[d], a);
        g_att[base + (size_t)e*NPH] = a * inv;
    }
}

// ---------------- K6: 5x5 conv (64 -> 128) on checkerboard-sparse att (R7 form) ----------------
__global__ __launch_bounds__(256) void k_conv5(const float* __restrict__ rb, float* __restrict__ out){
    __shared__ float attsm[1600];
    __shared__ float wsm[6400];
    int tid = threadIdx.x;
    int b = blockIdx.z >> 2, cog = blockIdx.z & 3;
    int i0 = blockIdx.y*16, j0 = blockIdx.x*16;

    int p = tid >> 7;
    int id = tid & 127; int ty = id >> 3; int txp = id & 7;
    int tx = 2*txp + ((ty + p) & 1);

    int tc[5];
    #pragma unroll
    for (int kj = 0; kj < 5; kj++) tc[kj] = ((tx + kj - 2) >> 1) + 1;

    float acc[32];
    #pragma unroll
    for (int c = 0; c < 32; c++) acc[c] = 0.f;

    for (int cc0 = 0; cc0 < 64; cc0 += 8){
        __syncthreads();
        for (int idx = tid; idx < 1600; idx += 256){
            int ci = idx/200; int r2 = idx - ci*200; int rr = r2/10; int cl = r2 - rr*10;
            int grow = i0 - 2 + rr; int gcol = (j0 >> 1) - 1 + cl;
            float v = 0.f;
            if (grow >= 0 && grow < NH && gcol >= 0 && gcol < NWH)
                v = g_att[((size_t)(b*NC + cc0 + ci)*NH + grow)*NWH + gcol];
            attsm[idx] = v;
        }
        for (int idx = tid; idx < 6400; idx += 256){
            int col = idx & 31; int t2 = idx >> 5;
            wsm[idx] = g_rwt[(size_t)(cc0*25 + t2)*NC2 + cog*32 + col];
        }
        __syncthreads();
        #pragma unroll 2
        for (int ci = 0; ci < 8; ci++){
            const float* A = attsm + ci*200 + ty*10;
            const float4* Wf = (const float4*)(wsm + ci*800);
            if (p == 0){
                static const int KI[13] = {0,0,0,1,1,2,2,2,3,3,4,4,4};
                static const int KJ[13] = {0,2,4,1,3,0,2,4,1,3,0,2,4};
                #pragma unroll
                for (int t = 0; t < 13; t++){
                    float a = A[KI[t]*10 + tc[KJ[t]]];
                    const float4* wp = Wf + (KI[t]*5 + KJ[t])*8;
                    #pragma unroll
                    for (int c4 = 0; c4 < 8; c4++){
                        float4 w = wp[c4];
                        acc[4*c4+0] = fmaf(a, w.x, acc[4*c4+0]);
                        acc[4*c4+1] = fmaf(a, w.y, acc[4*c4+1]);
                        acc[4*c4+2] = fmaf(a, w.z, acc[4*c4+2]);
                        acc[4*c4+3] = fmaf(a, w.w, acc[4*c4+3]);
                    }
                }
            } else {
                static const int KI2[12] = {0,0,1,1,1,2,2,3,3,3,4,4};
                static const int KJ2[12] = {1,3,0,2,4,1,3,0,2,4,1,3};
                #pragma unroll
                for (int t = 0; t < 12; t++){
                    float a = A[KI2[t]*10 + tc[KJ2[t]]];
                    const float4* wp = Wf + (KI2[t]*5 + KJ2[t])*8;
                    #pragma unroll
                    for (int c4 = 0; c4 < 8; c4++){
                        float4 w = wp[c4];
                        acc[4*c4+0] = fmaf(a, w.x, acc[4*c4+0]);
                        acc[4*c4+1] = fmaf(a, w.y, acc[4*c4+1]);
                        acc[4*c4+2] = fmaf(a, w.z, acc[4*c4+2]);
                        acc[4*c4+3] = fmaf(a, w.w, acc[4*c4+3]);
                    }
                }
            }
        }
    }
    int i_ = i0 + ty, j_ = j0 + tx;
    size_t ob = ((size_t)(b*NC2 + cog*32)*NH + i_)*NW + j_;
    #pragma unroll
    for (int c = 0; c < 32; c++)
        out[ob + (size_t)c*NPIX] = acc[c] + rb[cog*32 + c];
}

// ---------------- K7: m1 = gelu(1x1 128->256), cp.async double-buffered ----------------
__global__ __launch_bounds__(256) void k_gemm_m1(const float* __restrict__ X, const float* __restrict__ bias){
    __shared__ float Xs[2][16][132];
    __shared__ float Ws[2][16][132];
    int tid = threadIdx.x; int tx = tid & 15, ty = tid >> 4;
    int cot = blockIdx.x;
    int px0 = blockIdx.y*128;
    int b = blockIdx.z;
    float acc[8][8];
    #pragma unroll
    for (int i = 0; i < 8; i++)
        #pragma unroll
        for (int j = 0; j < 8; j++) acc[i][j] = 0.f;

    const float* Xg = X + (size_t)b*NC2*NPIX + px0;
    int f0 = tid, f1 = tid + 256;
    int k_0 = f0 >> 5, c_0 = (f0 & 31)*4;
    int k_1 = f1 >> 5, c_1 = (f1 & 31)*4;

    cpa16(s2u(&Xs[0][k_0][c_0]), Xg + (size_t)k_0*NPIX + c_0);
    cpa16(s2u(&Xs[0][k_1][c_1]), Xg + (size_t)k_1*NPIX + c_1);
    cpa16(s2u(&Ws[0][k_0][c_0]), &g_m1wt[(size_t)k_0*NC4 + cot*128 + c_0]);
    cpa16(s2u(&Ws[0][k_1][c_1]), &g_m1wt[(size_t)k_1*NC4 + cot*128 + c_1]);
    CPA_COMMIT();

    for (int s = 0; s < 8; s++){
        int buf = s & 1;
        if (s < 7){
            int nb = buf ^ 1, k0 = (s+1)*16;
            cpa16(s2u(&Xs[nb][k_0][c_0]), Xg + (size_t)(k0+k_0)*NPIX + c_0);
            cpa16(s2u(&Xs[nb][k_1][c_1]), Xg + (size_t)(k0+k_1)*NPIX + c_1);
            cpa16(s2u(&Ws[nb][k_0][c_0]), &g_m1wt[(size_t)(k0+k_0)*NC4 + cot*128 + c_0]);
            cpa16(s2u(&Ws[nb][k_1][c_1]), &g_m1wt[(size_t)(k0+k_1)*NC4 + cot*128 + c_1]);
            CPA_COMMIT();
            CPA_WAIT1();
        } else {
            CPA_WAIT0();
        }
        __syncthreads();
        #pragma unroll
        for (int k = 0; k < 16; k++){
            float4 x0 = *(const float4*)&Xs[buf][k][tx*8];
            float4 x1 = *(const float4*)&Xs[buf][k][tx*8+4];
            float4 w0 = *(const float4*)&Ws[buf][k][ty*8];
            float4 w1 = *(const float4*)&Ws[buf][k][ty*8+4];
            float xv[8] = {x0.x,x0.y,x0.z,x0.w,x1.x,x1.y,x1.z,x1.w};
            float wv[8] = {w0.x,w0.y,w0.z,w0.w,w1.x,w1.y,w1.z,w1.w};
            #pragma unroll
            for (int i = 0; i < 8; i++)
                #pragma unroll
                for (int j = 0; j < 8; j++)
                    acc[i][j] = fmaf(wv[i], xv[j], acc[i][j]);
        }
        __syncthreads();
    }
    #pragma unroll
    for (int i = 0; i < 8; i++){
        int co = cot*128 + ty*8 + i;
        float bb = bias[co];
        float* dst = &g_m1v[((size_t)(b*NC4 + co))*NPIX + px0 + tx*8];
        float4 o0, o1;
        o0.x = gelu_f(acc[i][0]+bb); o0.y = gelu_f(acc[i][1]+bb);
        o0.z = gelu_f(acc[i][2]+bb); o0.w = gelu_f(acc[i][3]+bb);
        o1.x = gelu_f(acc[i][4]+bb); o1.y = gelu_f(acc[i][5]+bb);
        o1.z = gelu_f(acc[i][6]+bb); o1.w = gelu_f(acc[i][7]+bb);
        *(float4*)dst = o0;
        *(float4*)(dst+4) = o1;
    }
}

// ---------------- K8: m2 = gelu(depthwise 3x3 on 256 ch), 4 px/thread float4 ----------------
__global__ __launch_bounds__(256) void k_m2dw(const float* __restrict__ w, const float* __restrict__ bias){
    int gid = blockIdx.x*256 + threadIdx.x;
    int jq = gid & 63; int i_ = (gid >> 6) & 255; int bc = gid >> 14; int c = bc & 255;
    int j4 = jq*4;
    const float* s = g_m1v + (size_t)bc*NPIX;
    float* dsto = g_m2v + (size_t)bc*NPIX + i_*NW + j4;
    const float* wc = w + c*9;
    float bb = bias[c];

    if (i_ > 0 && i_ < 255 && j4 >= 4 && j4 <= 248){
        float a0 = bb, a1 = bb, a2 = bb, a3 = bb;
        #pragma unroll
        for (int r = 0; r < 3; r++){
            const float* row = s + (i_ - 1 + r)*NW + j4;
            float4 m = *(const float4*)row;
            float l = row[-1], h = row[4];
            float w0 = wc[r*3], w1 = wc[r*3+1], w2 = wc[r*3+2];
            a0 = fmaf(w0, l,   a0); a0 = fmaf(w1, m.x, a0); a0 = fmaf(w2, m.y, a0);
            a1 = fmaf(w0, m.x, a1); a1 = fmaf(w1, m.y, a1); a1 = fmaf(w2, m.z, a1);
            a2 = fmaf(w0, m.y, a2); a2 = fmaf(w1, m.z, a2); a2 = fmaf(w2, m.w, a2);
            a3 = fmaf(w0, m.z, a3); a3 = fmaf(w1, m.w, a3); a3 = fmaf(w2, h,   a3);
        }
        float4 o;
        o.x = gelu_f(a0); o.y = gelu_f(a1); o.z = gelu_f(a2); o.w = gelu_f(a3);
        *(float4*)dsto = o;
    } else {
        #pragma unroll
        for (int t = 0; t < 4; t++){
            int j_ = j4 + t;
            float acc = bb;
            #pragma unroll
            for (int di = -1; di <= 1; di++)
                #pragma unroll
                for (int dj = -1; dj <= 1; dj++){
                    int ii = i_ + di, jj = j_ + dj;
                    if (ii >= 0 && ii < NH && jj >= 0 && jj < NW)
                        acc = fmaf(wc[(di+1)*3 + (dj+1)], s[ii*NW + jj], acc);
                }
            dsto[t] = gelu_f(acc);
        }
    }
}

// ---------------- K9: out += bias + 1x1 256->128, cp.async double-buffered ----------------
__global__ __launch_bounds__(256) void k_gemm_m3(const float* __restrict__ bias, float* __restrict__ out){
    __shared__ float Xs[2][16][132];
    __shared__ float Ws[2][16][132];
    int tid = threadIdx.x; int tx = tid & 15, ty = tid >> 4;
    int px0 = blockIdx.y*128;
    int b = blockIdx.z;
    float acc[8][8];
    #pragma unroll
    for (int i = 0; i < 8; i++)
        #pragma unroll
        for (int j = 0; j < 8; j++) acc[i][j] = 0.f;

    const float* Xg = g_m2v + (size_t)b*NC4*NPIX + px0;
    int f0 = tid, f1 = tid + 256;
    int k_0 = f0 >> 5, c_0 = (f0 & 31)*4;
    int k_1 = f1 >> 5, c_1 = (f1 & 31)*4;

    cpa16(s2u(&Xs[0][k_0][c_0]), Xg + (size_t)k_0*NPIX + c_0);
    cpa16(s2u(&Xs[0][k_1][c_1]), Xg + (size_t)k_1*NPIX + c_1);
    cpa16(s2u(&Ws[0][k_0][c_0]), &g_m3wt[(size_t)k_0*NC2 + c_0]);
    cpa16(s2u(&Ws[0][k_1][c_1]), &g_m3wt[(size_t)k_1*NC2 + c_1]);
    CPA_COMMIT();

    for (int s = 0; s < 16; s++){
        int buf = s & 1;
        if (s < 15){
            int nb = buf ^ 1, k0 = (s+1)*16;
            cpa16(s2u(&Xs[nb][k_0][c_0]), Xg + (size_t)(k0+k_0)*NPIX + c_0);
            cpa16(s2u(&Xs[nb][k_1][c_1]), Xg + (size_t)(k0+k_1)*NPIX + c_1);
            cpa16(s2u(&Ws[nb][k_0][c_0]), &g_m3wt[(size_t)(k0+k_0)*NC2 + c_0]);
            cpa16(s2u(&Ws[nb][k_1][c_1]), &g_m3wt[(size_t)(k0+k_1)*NC2 + c_1]);
            CPA_COMMIT();
            CPA_WAIT1();
        } else {
            CPA_WAIT0();
        }
        __syncthreads();
        #pragma unroll
        for (int k = 0; k < 16; k++){
            float4 x0 = *(const float4*)&Xs[buf][k][tx*8];
            float4 x1 = *(const float4*)&Xs[buf][k][tx*8+4];
            float4 w0 = *(const float4*)&Ws[buf][k][ty*8];
            float4 w1 = *(const float4*)&Ws[buf][k][ty*8+4];
            float xv[8] = {x0.x,x0.y,x0.z,x0.w,x1.x,x1.y,x1.z,x1.w};
            float wv[8] = {w0.x,w0.y,w0.z,w0.w,w1.x,w1.y,w1.z,w1.w};
            #pragma unroll
            for (int i = 0; i < 8; i++)
                #pragma unroll
                for (int j = 0; j < 8; j++)
                    acc[i][j] = fmaf(wv[i], xv[j], acc[i][j]);
        }
        __syncthreads();
    }
    #pragma unroll
    for (int i = 0; i < 8; i++){
        int co = ty*8 + i;
        float bb = bias[co];
        float* dst = &out[((size_t)(b*NC2 + co))*NPIX + px0 + tx*8];
        float4 r0 = *(const float4*)dst;
        float4 r1 = *(const float4*)(dst+4);
        float4 o0, o1;
        o0.x = acc[i][0]+bb+r0.x; o0.y = acc[i][1]+bb+r0.y;
        o0.z = acc[i][2]+bb+r0.z; o0.w = acc[i][3]+bb+r0.w;
        o1.x = acc[i][4]+bb+r1.x; o1.y = acc[i][5]+bb+r1.y;
        o1.z = acc[i][6]+bb+r1.z; o1.w = acc[i][7]+bb+r1.w;
        *(float4*)dst = o0;
        *(float4*)(dst+4) = o1;
    }
}

extern "C" void kernel_launch(void* const* d_in, const int* in_sizes, int n_in,
                              void* d_out, int out_size){
    const float* x1  = (const float*)d_in[0];
    const float* x2  = (const float*)d_in[1];
    const float* q1w = (const float*)d_in[2];  const float* q1b = (const float*)d_in[3];
    const float* q2w = (const float*)d_in[4];  const float* q2b = (const float*)d_in[5];
    const float* k1w = (const float*)d_in[6];  const float* k1b = (const float*)d_in[7];
    const float* k2w = (const float*)d_in[8];  const float* k2b = (const float*)d_in[9];
    const float* v1w = (const float*)d_in[10]; const float* v1b = (const float*)d_in[11];
    const float* v2w = (const float*)d_in[12]; const float* v2b = (const float*)d_in[13];
    const float* rw  = (const float*)d_in[14]; const float* rb  = (const float*)d_in[15];
    const float* m1w = (const float*)d_in[16]; const float* m1b = (const float*)d_in[17];
    const float* m2w = (const float*)d_in[18]; const float* m2b = (const float*)d_in[19];
    const float* m3w = (const float*)d_in[20]; const float* m3b = (const float*)d_in[21];
    float* out = (float*)d_out;

    k_prep<<<800, 256>>>(rw, m1w, m3w);
    k_qkv1<<<1024, 256>>>(x1, x2, q1w, q1b, k1w, k1b, v1w, v1b);
    k_dws<<<dim3(16384, 3), 256>>>(q2w, q2b, k2w, k2b, v2w, v2b, q1b, k1b);
    k_kstats<<<256, 1024>>>();
    k_ctx<<<dim3(16, 16), 256>>>();
    k_att<<<dim3(128, 16), 256>>>();
    k_conv5<<<dim3(16, 16, 16), 256>>>(rb, out);
    k_gemm_m1<<<dim3(2, 512, 4), 256>>>(out, m1b);
    k_m2dw<<<65536, 256>>>(m2w, m2b);
    k_gemm_m3<<<dim3(1, 512, 4), 256>>>(m3b, out);
}